// round 3
// baseline (speedup 1.0000x reference)
#include <cuda_runtime.h>
#include <cuda_bf16.h>

#define N_PTS   32768
#define S_NBR   32
#define C_IN    64
#define C_OUT   128
#define NS      (N_PTS * S_NBR)   // 1048576
#define EPSBN   1e-5f

// Scratch (device globals; no allocation allowed)
__device__ float g_ypre[C_OUT * N_PTS];   // [o][n] 16 MB  (feature pre-BN)
__device__ float g_rpre[C_OUT * N_PTS];   // [o][n] 16 MB  (residual pre-BN)
__device__ float g_cA[2 * C_OUT];         // BN scale  [feat | res]
__device__ float g_cB[2 * C_OUT];         // BN shift  [feat | res]

// ---------------------------------------------------------------------------
// Fully fused kernel. Block = 256 threads, 32 points.
// Phase 1 (aggregation, shuffle-free): thread = (channel c, point slot p).
//   Each thread reads its OWN full 128B line np[3+c][n][0..31] via 8x LDG.128
//   and reduces over s privately in registers. Positions staged in smem.
// Phase 2 (feature GEMV 64->128): warp = 16-output slab, lane = point.
// Phase 3 (residual GEMV 64->128): same tiling, reusing smem buffers.
__global__ __launch_bounds__(256) void k_fused(
    const float* __restrict__ xyz,     // [N][3]
    const float* __restrict__ np,      // [67][N][S]
    const float* __restrict__ pf,      // [64][N]
    const float* __restrict__ Wint,    // [64][3]
    const float* __restrict__ bint,    // [64]
    const float* __restrict__ Wfeat,   // [128][64]
    const float* __restrict__ bfeat,   // [128]
    const float* __restrict__ Wres,    // [128][64]
    const float* __restrict__ bres)    // [128]
{
    __shared__ float  spos[3 * 32 * 32];      // 12 KB: [k][pt][s] relative pos
    __shared__ float  aggs[C_IN][33];         // padded (also reused as pf tile)
    __shared__ float4 Ws[C_OUT * (C_IN/4)];   // 32 KB (Wfeat, then Wres)
    __shared__ float  bs[C_OUT];
    __shared__ float4 wq[C_IN];               // {w0,w1,w2,bias} of Wint

    int tid  = threadIdx.x;
    int warp = tid >> 5;
    int lane = tid & 31;
    int n0   = blockIdx.x * 32;

    // ---- stage Wint rows + Wfeat + positions ----
    if (tid < C_IN)
        wq[tid] = make_float4(Wint[tid*3+0], Wint[tid*3+1], Wint[tid*3+2], bint[tid]);
    {
        const float4* W4 = (const float4*)Wfeat;
        #pragma unroll
        for (int i = tid; i < C_OUT * (C_IN/4); i += 256) Ws[i] = W4[i];
        if (tid < C_OUT) bs[tid] = bfeat[tid];
    }
    #pragma unroll
    for (int i = tid; i < 3 * 1024; i += 256) {
        int k  = i >> 10;          // coord 0..2
        int r  = i & 1023;         // pt*32 + s
        int pt = r >> 5;
        spos[i] = np[k * NS + (n0 << 5) + r] - xyz[(n0 + pt) * 3 + k];
    }
    __syncthreads();

    // ---- Phase 1: shuffle-free aggregation ----
    int c = tid & 63;              // channel
    int p = tid >> 6;              // point sub-slot 0..3
    float4 w = wq[c];

    #pragma unroll
    for (int q = 0; q < 8; q++) {
        int pt = (q << 2) | p;                 // point in block 0..31
        int n  = n0 + pt;
        const float4* __restrict__ fp =
            (const float4*)(np + (size_t)(3 + c) * NS + ((size_t)n << 5));
        const float* psx = &spos[0 * 1024 + (pt << 5)];
        const float* psy = &spos[1 * 1024 + (pt << 5)];
        const float* psz = &spos[2 * 1024 + (pt << 5)];

        float acc = 0.0f;
        #pragma unroll
        for (int s4 = 0; s4 < 8; s4++) {
            float4 f = fp[s4];
            int s = s4 << 2;
            float h0 = fmaf(w.x, psx[s+0], fmaf(w.y, psy[s+0], fmaf(w.z, psz[s+0], w.w)));
            float h1 = fmaf(w.x, psx[s+1], fmaf(w.y, psy[s+1], fmaf(w.z, psz[s+1], w.w)));
            float h2 = fmaf(w.x, psx[s+2], fmaf(w.y, psy[s+2], fmaf(w.z, psz[s+2], w.w)));
            float h3 = fmaf(w.x, psx[s+3], fmaf(w.y, psy[s+3], fmaf(w.z, psz[s+3], w.w)));
            acc = fmaf(fmaxf(h0, 0.0f), f.x, acc);
            acc = fmaf(fmaxf(h1, 0.0f), f.y, acc);
            acc = fmaf(fmaxf(h2, 0.0f), f.z, acc);
            acc = fmaf(fmaxf(h3, 0.0f), f.w, acc);
        }
        aggs[c][pt] = acc;     // pitch 33 -> conflict-free
    }
    __syncthreads();

    // ---- Phase 2: feature GEMV, thread = (16 outputs, 1 point) ----
    int o0 = warp * 16;
    {
        float acc[16];
        #pragma unroll
        for (int oi = 0; oi < 16; oi++) acc[oi] = bs[o0 + oi];

        #pragma unroll 4
        for (int c4 = 0; c4 < C_IN/4; c4++) {
            float f0 = aggs[c4*4+0][lane];
            float f1 = aggs[c4*4+1][lane];
            float f2 = aggs[c4*4+2][lane];
            float f3 = aggs[c4*4+3][lane];
            #pragma unroll
            for (int oi = 0; oi < 16; oi++) {
                float4 w4 = Ws[(o0 + oi) * (C_IN/4) + c4];
                acc[oi] = fmaf(f0, w4.x, acc[oi]);
                acc[oi] = fmaf(f1, w4.y, acc[oi]);
                acc[oi] = fmaf(f2, w4.z, acc[oi]);
                acc[oi] = fmaf(f3, w4.w, acc[oi]);
            }
        }
        int n = n0 + lane;
        #pragma unroll
        for (int oi = 0; oi < 16; oi++)
            g_ypre[(o0 + oi) * N_PTS + n] = acc[oi];   // coalesced
    }
    __syncthreads();   // everyone done reading aggs/Ws before overwrite

    // ---- reload smem with residual operands ----
    {
        const float4* W4 = (const float4*)Wres;
        #pragma unroll
        for (int i = tid; i < C_OUT * (C_IN/4); i += 256) Ws[i] = W4[i];
        if (tid < C_OUT) bs[tid] = bres[tid];
    }
    #pragma unroll
    for (int i = tid; i < C_IN * 32; i += 256) {
        int cc = i >> 5, col = i & 31;
        aggs[cc][col] = pf[cc * N_PTS + n0 + col];   // coalesced
    }
    __syncthreads();

    // ---- Phase 3: residual GEMV ----
    {
        float acc[16];
        #pragma unroll
        for (int oi = 0; oi < 16; oi++) acc[oi] = bs[o0 + oi];

        #pragma unroll 4
        for (int c4 = 0; c4 < C_IN/4; c4++) {
            float f0 = aggs[c4*4+0][lane];
            float f1 = aggs[c4*4+1][lane];
            float f2 = aggs[c4*4+2][lane];
            float f3 = aggs[c4*4+3][lane];
            #pragma unroll
            for (int oi = 0; oi < 16; oi++) {
                float4 w4 = Ws[(o0 + oi) * (C_IN/4) + c4];
                acc[oi] = fmaf(f0, w4.x, acc[oi]);
                acc[oi] = fmaf(f1, w4.y, acc[oi]);
                acc[oi] = fmaf(f2, w4.z, acc[oi]);
                acc[oi] = fmaf(f3, w4.w, acc[oi]);
            }
        }
        int n = n0 + lane;
        #pragma unroll
        for (int oi = 0; oi < 16; oi++)
            g_rpre[(o0 + oi) * N_PTS + n] = acc[oi];
    }
}

// ---------------------------------------------------------------------------
// BN stats: one block per (channel, path). No atomics. Emits scale/shift.
__global__ __launch_bounds__(256) void k_stats(
    const float* __restrict__ gf, const float* __restrict__ btf,
    const float* __restrict__ gr, const float* __restrict__ btr)
{
    __shared__ float ws1[8], ws2[8];

    int o   = blockIdx.x & (C_OUT - 1);
    int buf = blockIdx.x >> 7;
    int tid = threadIdx.x;

    const float4* src = (const float4*)((buf ? g_rpre : g_ypre) + o * N_PTS);

    float s1 = 0.0f, s2 = 0.0f;
    #pragma unroll 4
    for (int i = tid; i < N_PTS/4; i += 256) {
        float4 v = src[i];
        s1 += v.x + v.y + v.z + v.w;
        s2 += v.x*v.x + v.y*v.y + v.z*v.z + v.w*v.w;
    }
    #pragma unroll
    for (int off = 16; off; off >>= 1) {
        s1 += __shfl_xor_sync(0xffffffffu, s1, off);
        s2 += __shfl_xor_sync(0xffffffffu, s2, off);
    }
    int warp = tid >> 5, lane = tid & 31;
    if (lane == 0) { ws1[warp] = s1; ws2[warp] = s2; }
    __syncthreads();
    if (tid == 0) {
        float t1 = 0.0f, t2 = 0.0f;
        #pragma unroll
        for (int w = 0; w < 8; w++) { t1 += ws1[w]; t2 += ws2[w]; }
        const float inv = 1.0f / (float)N_PTS;
        float mean = t1 * inv;
        float var  = t2 * inv - mean * mean;
        float gamma = buf ? gr[o] : gf[o];
        float beta  = buf ? btr[o] : btf[o];
        float A = gamma * rsqrtf(var + EPSBN);
        g_cA[buf * C_OUT + o] = A;
        g_cB[buf * C_OUT + o] = beta - mean * A;
    }
}

// ---------------------------------------------------------------------------
// Finalize: BN affine + ReLU on both paths, add, float4 throughout.
__global__ __launch_bounds__(256) void k_final(float* __restrict__ out)
{
    int i4 = blockIdx.x * 256 + threadIdx.x;    // float4 index
    int o  = i4 >> 13;                          // channel (N/4 = 8192 per row)

    float Af = g_cA[o],         Bf = g_cB[o];
    float Ar = g_cA[C_OUT + o], Br = g_cB[C_OUT + o];

    float4 y = ((const float4*)g_ypre)[i4];
    float4 r = ((const float4*)g_rpre)[i4];
    float4 v;
    v.x = fmaxf(fmaf(y.x, Af, Bf), 0.0f) + fmaxf(fmaf(r.x, Ar, Br), 0.0f);
    v.y = fmaxf(fmaf(y.y, Af, Bf), 0.0f) + fmaxf(fmaf(r.y, Ar, Br), 0.0f);
    v.z = fmaxf(fmaf(y.z, Af, Bf), 0.0f) + fmaxf(fmaf(r.z, Ar, Br), 0.0f);
    v.w = fmaxf(fmaf(y.w, Af, Bf), 0.0f) + fmaxf(fmaf(r.w, Ar, Br), 0.0f);
    ((float4*)out)[i4] = v;
}

// ---------------------------------------------------------------------------
extern "C" void kernel_launch(void* const* d_in, const int* in_sizes, int n_in,
                              void* d_out, int out_size) {
    const float* xyz   = (const float*)d_in[0];   // (1, N, 3)
    const float* pf    = (const float*)d_in[1];   // (1, 64, N)
    const float* np    = (const float*)d_in[2];   // (1, 67, N, 32)
    const float* Wint  = (const float*)d_in[3];
    const float* bint  = (const float*)d_in[4];
    const float* Wfeat = (const float*)d_in[5];
    const float* bfeat = (const float*)d_in[6];
    const float* gfeat = (const float*)d_in[7];
    const float* befeat= (const float*)d_in[8];
    const float* Wres  = (const float*)d_in[9];
    const float* bres  = (const float*)d_in[10];
    const float* gres  = (const float*)d_in[11];
    const float* beres = (const float*)d_in[12];
    float* out = (float*)d_out;

    k_fused<<<N_PTS / 32, 256>>>(xyz, np, pf, Wint, bint,
                                 Wfeat, bfeat, Wres, bres);
    k_stats<<<2 * C_OUT, 256>>>(gfeat, befeat, gres, beres);
    k_final<<<(C_OUT * N_PTS / 4) / 256, 256>>>(out);
}

// round 4
// speedup vs baseline: 1.0690x; 1.0690x over previous
#include <cuda_runtime.h>
#include <cuda_bf16.h>

#define N_PTS   32768
#define S_NBR   32
#define C_IN    64
#define C_OUT   128
#define NS      (N_PTS * S_NBR)   // 1048576
#define EPSBN   1e-5f

// Scratch (device globals; no allocation allowed)
__device__ float g_ypre[C_OUT * N_PTS];   // [o][n] 16 MB  (feature pre-BN)
__device__ float g_rpre[C_OUT * N_PTS];   // [o][n] 16 MB  (residual pre-BN)
__device__ float g_cA[2 * C_OUT];         // BN scale  [feat | res]
__device__ float g_cB[2 * C_OUT];         // BN shift  [feat | res]

// ---------------------------------------------------------------------------
// Fully fused kernel. Block = 256 threads, 32 points.
//
// Phase 1 (aggregation): lane = (idx = lane>>3, s4 = lane&7).
//   A warp's LDG.128 covers 512B contiguous (4 consecutive points' 128B
//   s-lines of one channel). Each thread reduces its 4 samples in registers;
//   cross-lane reduce is only 3 shfl_xor over the 8-lane group.
//   Warp w owns channels [8w, 8w+8) x all 32 points.
// Phase 2 (feature GEMV 64->128): warp = 16-output slab, lane = point.
// Phase 3 (residual GEMV): same tiling, smem buffers reloaded.
__global__ __launch_bounds__(256) void k_fused(
    const float* __restrict__ xyz,     // [N][3]
    const float* __restrict__ np,      // [67][N][S]
    const float* __restrict__ pf,      // [64][N]
    const float* __restrict__ Wint,    // [64][3]
    const float* __restrict__ bint,    // [64]
    const float* __restrict__ Wfeat,   // [128][64]
    const float* __restrict__ bfeat,   // [128]
    const float* __restrict__ Wres,    // [128][64]
    const float* __restrict__ bres)    // [128]
{
    __shared__ __align__(16) float spos[3 * 32 * 32];  // 12 KB: [k][pt][s]
    __shared__ float  aggs[C_IN][33];                  // padded; reused as pf tile
    __shared__ float4 Ws[C_OUT * (C_IN/4)];            // 32 KB
    __shared__ float  bs[C_OUT];
    __shared__ float4 wq[C_IN];                        // {w0,w1,w2,bias}

    int tid  = threadIdx.x;
    int warp = tid >> 5;
    int lane = tid & 31;
    int n0   = blockIdx.x * 32;

    // ---- stage Wint + Wfeat + relative positions ----
    if (tid < C_IN)
        wq[tid] = make_float4(Wint[tid*3+0], Wint[tid*3+1], Wint[tid*3+2], bint[tid]);
    {
        const float4* W4 = (const float4*)Wfeat;
        #pragma unroll
        for (int i = tid; i < C_OUT * (C_IN/4); i += 256) Ws[i] = W4[i];
        if (tid < C_OUT) bs[tid] = bfeat[tid];
    }
    #pragma unroll
    for (int i = tid; i < 3 * 1024; i += 256) {
        int k  = i >> 10;          // coord 0..2
        int r  = i & 1023;         // pt*32 + s
        int pt = r >> 5;
        spos[i] = np[k * NS + (n0 << 5) + r] - xyz[(n0 + pt) * 3 + k];
    }
    __syncthreads();

    // ---- Phase 1: aggregation ----
    {
        int s4  = lane & 7;        // 16B chunk within a 128B s-line
        int idx = lane >> 3;       // point within group of 4
        const float4* sp4 = (const float4*)spos;   // [k][pt][s4] as float4

        #pragma unroll
        for (int ci = 0; ci < 8; ci++) {
            int c = (warp << 3) | ci;
            float4 w = wq[c];
            const float* fbase = np + (size_t)(3 + c) * NS + ((size_t)n0 << 5);

            #pragma unroll 2
            for (int ptg = 0; ptg < 8; ptg++) {
                int pt = (ptg << 2) | idx;
                // coalesced 512B per warp instruction
                float4 f  = *(const float4*)(fbase + (pt << 5) + (s4 << 2));
                float4 px = sp4[0 * 256 + (pt << 3) + s4];
                float4 py = sp4[1 * 256 + (pt << 3) + s4];
                float4 pz = sp4[2 * 256 + (pt << 3) + s4];

                float h0 = fmaf(w.x, px.x, fmaf(w.y, py.x, fmaf(w.z, pz.x, w.w)));
                float h1 = fmaf(w.x, px.y, fmaf(w.y, py.y, fmaf(w.z, pz.y, w.w)));
                float h2 = fmaf(w.x, px.z, fmaf(w.y, py.z, fmaf(w.z, pz.z, w.w)));
                float h3 = fmaf(w.x, px.w, fmaf(w.y, py.w, fmaf(w.z, pz.w, w.w)));

                float acc;
                acc  = fmaxf(h0, 0.0f) * f.x;
                acc  = fmaf(fmaxf(h1, 0.0f), f.y, acc);
                acc  = fmaf(fmaxf(h2, 0.0f), f.z, acc);
                acc  = fmaf(fmaxf(h3, 0.0f), f.w, acc);

                // reduce over s4 (lane bits 0..2): 3 shfls
                acc += __shfl_xor_sync(0xffffffffu, acc, 1);
                acc += __shfl_xor_sync(0xffffffffu, acc, 2);
                acc += __shfl_xor_sync(0xffffffffu, acc, 4);
                if (s4 == 0) aggs[c][pt] = acc;
            }
        }
    }
    __syncthreads();

    // ---- Phase 2: feature GEMV, thread = (16 outputs, 1 point) ----
    int o0 = warp * 16;
    {
        float acc[16];
        #pragma unroll
        for (int oi = 0; oi < 16; oi++) acc[oi] = bs[o0 + oi];

        #pragma unroll 4
        for (int c4 = 0; c4 < C_IN/4; c4++) {
            float f0 = aggs[c4*4+0][lane];
            float f1 = aggs[c4*4+1][lane];
            float f2 = aggs[c4*4+2][lane];
            float f3 = aggs[c4*4+3][lane];
            #pragma unroll
            for (int oi = 0; oi < 16; oi++) {
                float4 w4 = Ws[(o0 + oi) * (C_IN/4) + c4];
                acc[oi] = fmaf(f0, w4.x, acc[oi]);
                acc[oi] = fmaf(f1, w4.y, acc[oi]);
                acc[oi] = fmaf(f2, w4.z, acc[oi]);
                acc[oi] = fmaf(f3, w4.w, acc[oi]);
            }
        }
        int n = n0 + lane;
        #pragma unroll
        for (int oi = 0; oi < 16; oi++)
            g_ypre[(o0 + oi) * N_PTS + n] = acc[oi];   // coalesced
    }
    __syncthreads();   // done reading aggs/Ws before overwrite

    // ---- reload smem with residual operands ----
    {
        const float4* W4 = (const float4*)Wres;
        #pragma unroll
        for (int i = tid; i < C_OUT * (C_IN/4); i += 256) Ws[i] = W4[i];
        if (tid < C_OUT) bs[tid] = bres[tid];
    }
    #pragma unroll
    for (int i = tid; i < C_IN * 32; i += 256) {
        int cc = i >> 5, col = i & 31;
        aggs[cc][col] = pf[cc * N_PTS + n0 + col];   // coalesced
    }
    __syncthreads();

    // ---- Phase 3: residual GEMV ----
    {
        float acc[16];
        #pragma unroll
        for (int oi = 0; oi < 16; oi++) acc[oi] = bs[o0 + oi];

        #pragma unroll 4
        for (int c4 = 0; c4 < C_IN/4; c4++) {
            float f0 = aggs[c4*4+0][lane];
            float f1 = aggs[c4*4+1][lane];
            float f2 = aggs[c4*4+2][lane];
            float f3 = aggs[c4*4+3][lane];
            #pragma unroll
            for (int oi = 0; oi < 16; oi++) {
                float4 w4 = Ws[(o0 + oi) * (C_IN/4) + c4];
                acc[oi] = fmaf(f0, w4.x, acc[oi]);
                acc[oi] = fmaf(f1, w4.y, acc[oi]);
                acc[oi] = fmaf(f2, w4.z, acc[oi]);
                acc[oi] = fmaf(f3, w4.w, acc[oi]);
            }
        }
        int n = n0 + lane;
        #pragma unroll
        for (int oi = 0; oi < 16; oi++)
            g_rpre[(o0 + oi) * N_PTS + n] = acc[oi];
    }
}

// ---------------------------------------------------------------------------
// BN stats: one block per (channel, path). No atomics. Emits scale/shift.
__global__ __launch_bounds__(256) void k_stats(
    const float* __restrict__ gf, const float* __restrict__ btf,
    const float* __restrict__ gr, const float* __restrict__ btr)
{
    __shared__ float ws1[8], ws2[8];

    int o   = blockIdx.x & (C_OUT - 1);
    int buf = blockIdx.x >> 7;
    int tid = threadIdx.x;

    const float4* src = (const float4*)((buf ? g_rpre : g_ypre) + o * N_PTS);

    float s1 = 0.0f, s2 = 0.0f;
    #pragma unroll 4
    for (int i = tid; i < N_PTS/4; i += 256) {
        float4 v = src[i];
        s1 += v.x + v.y + v.z + v.w;
        s2 += v.x*v.x + v.y*v.y + v.z*v.z + v.w*v.w;
    }
    #pragma unroll
    for (int off = 16; off; off >>= 1) {
        s1 += __shfl_xor_sync(0xffffffffu, s1, off);
        s2 += __shfl_xor_sync(0xffffffffu, s2, off);
    }
    int warp = tid >> 5, lane = tid & 31;
    if (lane == 0) { ws1[warp] = s1; ws2[warp] = s2; }
    __syncthreads();
    if (tid == 0) {
        float t1 = 0.0f, t2 = 0.0f;
        #pragma unroll
        for (int w = 0; w < 8; w++) { t1 += ws1[w]; t2 += ws2[w]; }
        const float inv = 1.0f / (float)N_PTS;
        float mean = t1 * inv;
        float var  = t2 * inv - mean * mean;
        float gamma = buf ? gr[o] : gf[o];
        float beta  = buf ? btr[o] : btf[o];
        float A = gamma * rsqrtf(var + EPSBN);
        g_cA[buf * C_OUT + o] = A;
        g_cB[buf * C_OUT + o] = beta - mean * A;
    }
}

// ---------------------------------------------------------------------------
// Finalize: BN affine + ReLU on both paths, add, float4 throughout.
__global__ __launch_bounds__(256) void k_final(float* __restrict__ out)
{
    int i4 = blockIdx.x * 256 + threadIdx.x;    // float4 index
    int o  = i4 >> 13;                          // channel (N/4 = 8192 per row)

    float Af = g_cA[o],         Bf = g_cB[o];
    float Ar = g_cA[C_OUT + o], Br = g_cB[C_OUT + o];

    float4 y = ((const float4*)g_ypre)[i4];
    float4 r = ((const float4*)g_rpre)[i4];
    float4 v;
    v.x = fmaxf(fmaf(y.x, Af, Bf), 0.0f) + fmaxf(fmaf(r.x, Ar, Br), 0.0f);
    v.y = fmaxf(fmaf(y.y, Af, Bf), 0.0f) + fmaxf(fmaf(r.y, Ar, Br), 0.0f);
    v.z = fmaxf(fmaf(y.z, Af, Bf), 0.0f) + fmaxf(fmaf(r.z, Ar, Br), 0.0f);
    v.w = fmaxf(fmaf(y.w, Af, Bf), 0.0f) + fmaxf(fmaf(r.w, Ar, Br), 0.0f);
    ((float4*)out)[i4] = v;
}

// ---------------------------------------------------------------------------
extern "C" void kernel_launch(void* const* d_in, const int* in_sizes, int n_in,
                              void* d_out, int out_size) {
    const float* xyz   = (const float*)d_in[0];   // (1, N, 3)
    const float* pf    = (const float*)d_in[1];   // (1, 64, N)
    const float* np    = (const float*)d_in[2];   // (1, 67, N, 32)
    const float* Wint  = (const float*)d_in[3];
    const float* bint  = (const float*)d_in[4];
    const float* Wfeat = (const float*)d_in[5];
    const float* bfeat = (const float*)d_in[6];
    const float* gfeat = (const float*)d_in[7];
    const float* befeat= (const float*)d_in[8];
    const float* Wres  = (const float*)d_in[9];
    const float* bres  = (const float*)d_in[10];
    const float* gres  = (const float*)d_in[11];
    const float* beres = (const float*)d_in[12];
    float* out = (float*)d_out;

    k_fused<<<N_PTS / 32, 256>>>(xyz, np, pf, Wint, bint,
                                 Wfeat, bfeat, Wres, bres);
    k_stats<<<2 * C_OUT, 256>>>(gfeat, befeat, gres, beres);
    k_final<<<(C_OUT * N_PTS / 4) / 256, 256>>>(out);
}

// round 5
// speedup vs baseline: 1.7087x; 1.5984x over previous
#include <cuda_runtime.h>
#include <cuda_bf16.h>

#define N_PTS   32768
#define S_NBR   32
#define C_IN    64
#define C_OUT   128
#define NS      (N_PTS * S_NBR)   // 1048576
#define EPSBN   1e-5f

// Scratch (device globals; no allocation allowed)
__device__ float g_ypre[C_OUT * N_PTS];   // [o][n] 16 MB  (feature pre-BN)
__device__ float g_rpre[C_OUT * N_PTS];   // [o][n] 16 MB  (residual pre-BN)
__device__ float g_cA[2 * C_OUT];         // BN scale  [feat | res]
__device__ float g_cB[2 * C_OUT];         // BN shift  [feat | res]

// ---------------------------------------------------------------------------
// Fully fused kernel. Block = 256 threads, 32 points.
//
// Phase 1 (aggregation): lane = (idx = lane>>3, s4 = lane&7).
//   Warp w owns channels [8w, 8w+8). Loop order: point-group OUTER (positions
//   loaded once into registers), channel INNER (only the feature LDG.128 and
//   a broadcast wq read per iteration). A warp's LDG.128 covers 512B
//   contiguous. Cross-lane reduce = 3 shfl_xor over the 8-lane s4 group.
// Phase 2 (feature GEMV 64->128): warp = 16-output slab, lane = point.
// Phase 3 (residual GEMV): same tiling, smem buffers reloaded.
__global__ __launch_bounds__(256) void k_fused(
    const float* __restrict__ xyz,     // [N][3]
    const float* __restrict__ np,      // [67][N][S]
    const float* __restrict__ pf,      // [64][N]
    const float* __restrict__ Wint,    // [64][3]
    const float* __restrict__ bint,    // [64]
    const float* __restrict__ Wfeat,   // [128][64]
    const float* __restrict__ bfeat,   // [128]
    const float* __restrict__ Wres,    // [128][64]
    const float* __restrict__ bres)    // [128]
{
    __shared__ __align__(16) float spos[3 * 32 * 32];  // 12 KB: [k][pt][s]
    __shared__ float  aggs[C_IN][33];                  // padded; reused as pf tile
    __shared__ float4 Ws[C_OUT * (C_IN/4)];            // 32 KB
    __shared__ float  bs[C_OUT];
    __shared__ float4 wq[C_IN];                        // {w0,w1,w2,bias}

    int tid  = threadIdx.x;
    int warp = tid >> 5;
    int lane = tid & 31;
    int n0   = blockIdx.x * 32;

    // ---- stage Wint + Wfeat + relative positions ----
    if (tid < C_IN)
        wq[tid] = make_float4(Wint[tid*3+0], Wint[tid*3+1], Wint[tid*3+2], bint[tid]);
    {
        const float4* W4 = (const float4*)Wfeat;
        #pragma unroll
        for (int i = tid; i < C_OUT * (C_IN/4); i += 256) Ws[i] = W4[i];
        if (tid < C_OUT) bs[tid] = bfeat[tid];
    }
    #pragma unroll
    for (int i = tid; i < 3 * 1024; i += 256) {
        int k  = i >> 10;          // coord 0..2
        int r  = i & 1023;         // pt*32 + s
        int pt = r >> 5;
        spos[i] = np[k * NS + (n0 << 5) + r] - xyz[(n0 + pt) * 3 + k];
    }
    __syncthreads();

    // ---- Phase 1: aggregation (positions register-resident) ----
    {
        int s4  = lane & 7;        // 16B chunk within a 128B s-line
        int idx = lane >> 3;       // point within group of 4
        int c0  = warp << 3;       // first channel this warp owns
        const float4* sp4 = (const float4*)spos;   // [k][pt][s4] as float4

        #pragma unroll
        for (int ptg = 0; ptg < 8; ptg++) {
            int pt = (ptg << 2) | idx;
            // positions for MY 4 samples: loaded once, reused for 8 channels
            float4 px = sp4[0 * 256 + (pt << 3) + s4];
            float4 py = sp4[1 * 256 + (pt << 3) + s4];
            float4 pz = sp4[2 * 256 + (pt << 3) + s4];

            const float* fb = np + (size_t)3 * NS
                            + (((size_t)(n0 + pt)) << 5) + (s4 << 2);

            #pragma unroll
            for (int ci = 0; ci < 8; ci++) {
                int c = c0 | ci;
                float4 w = wq[c];                      // LDS broadcast (1 wf)
                float4 f = *(const float4*)(fb + (size_t)c * NS);  // 512B/warp

                float h0 = fmaf(w.x, px.x, fmaf(w.y, py.x, fmaf(w.z, pz.x, w.w)));
                float h1 = fmaf(w.x, px.y, fmaf(w.y, py.y, fmaf(w.z, pz.y, w.w)));
                float h2 = fmaf(w.x, px.z, fmaf(w.y, py.z, fmaf(w.z, pz.z, w.w)));
                float h3 = fmaf(w.x, px.w, fmaf(w.y, py.w, fmaf(w.z, pz.w, w.w)));

                float acc;
                acc = fmaxf(h0, 0.0f) * f.x;
                acc = fmaf(fmaxf(h1, 0.0f), f.y, acc);
                acc = fmaf(fmaxf(h2, 0.0f), f.z, acc);
                acc = fmaf(fmaxf(h3, 0.0f), f.w, acc);

                // reduce over s4 (lane bits 0..2): 3 shfls
                acc += __shfl_xor_sync(0xffffffffu, acc, 1);
                acc += __shfl_xor_sync(0xffffffffu, acc, 2);
                acc += __shfl_xor_sync(0xffffffffu, acc, 4);
                if (s4 == 0) aggs[c][pt] = acc;
            }
        }
    }
    __syncthreads();

    // ---- Phase 2: feature GEMV, thread = (16 outputs, 1 point) ----
    int o0 = warp * 16;
    {
        float acc[16];
        #pragma unroll
        for (int oi = 0; oi < 16; oi++) acc[oi] = bs[o0 + oi];

        #pragma unroll 4
        for (int c4 = 0; c4 < C_IN/4; c4++) {
            float f0 = aggs[c4*4+0][lane];
            float f1 = aggs[c4*4+1][lane];
            float f2 = aggs[c4*4+2][lane];
            float f3 = aggs[c4*4+3][lane];
            #pragma unroll
            for (int oi = 0; oi < 16; oi++) {
                float4 w4 = Ws[(o0 + oi) * (C_IN/4) + c4];
                acc[oi] = fmaf(f0, w4.x, acc[oi]);
                acc[oi] = fmaf(f1, w4.y, acc[oi]);
                acc[oi] = fmaf(f2, w4.z, acc[oi]);
                acc[oi] = fmaf(f3, w4.w, acc[oi]);
            }
        }
        int n = n0 + lane;
        #pragma unroll
        for (int oi = 0; oi < 16; oi++)
            g_ypre[(o0 + oi) * N_PTS + n] = acc[oi];   // coalesced
    }
    __syncthreads();   // done reading aggs/Ws before overwrite

    // ---- reload smem with residual operands ----
    {
        const float4* W4 = (const float4*)Wres;
        #pragma unroll
        for (int i = tid; i < C_OUT * (C_IN/4); i += 256) Ws[i] = W4[i];
        if (tid < C_OUT) bs[tid] = bres[tid];
    }
    #pragma unroll
    for (int i = tid; i < C_IN * 32; i += 256) {
        int cc = i >> 5, col = i & 31;
        aggs[cc][col] = pf[cc * N_PTS + n0 + col];   // coalesced
    }
    __syncthreads();

    // ---- Phase 3: residual GEMV ----
    {
        float acc[16];
        #pragma unroll
        for (int oi = 0; oi < 16; oi++) acc[oi] = bs[o0 + oi];

        #pragma unroll 4
        for (int c4 = 0; c4 < C_IN/4; c4++) {
            float f0 = aggs[c4*4+0][lane];
            float f1 = aggs[c4*4+1][lane];
            float f2 = aggs[c4*4+2][lane];
            float f3 = aggs[c4*4+3][lane];
            #pragma unroll
            for (int oi = 0; oi < 16; oi++) {
                float4 w4 = Ws[(o0 + oi) * (C_IN/4) + c4];
                acc[oi] = fmaf(f0, w4.x, acc[oi]);
                acc[oi] = fmaf(f1, w4.y, acc[oi]);
                acc[oi] = fmaf(f2, w4.z, acc[oi]);
                acc[oi] = fmaf(f3, w4.w, acc[oi]);
            }
        }
        int n = n0 + lane;
        #pragma unroll
        for (int oi = 0; oi < 16; oi++)
            g_rpre[(o0 + oi) * N_PTS + n] = acc[oi];
    }
}

// ---------------------------------------------------------------------------
// BN stats: one block per (channel, path). No atomics. Emits scale/shift.
__global__ __launch_bounds__(256) void k_stats(
    const float* __restrict__ gf, const float* __restrict__ btf,
    const float* __restrict__ gr, const float* __restrict__ btr)
{
    __shared__ float ws1[8], ws2[8];

    int o   = blockIdx.x & (C_OUT - 1);
    int buf = blockIdx.x >> 7;
    int tid = threadIdx.x;

    const float4* src = (const float4*)((buf ? g_rpre : g_ypre) + o * N_PTS);

    float s1 = 0.0f, s2 = 0.0f;
    #pragma unroll 4
    for (int i = tid; i < N_PTS/4; i += 256) {
        float4 v = src[i];
        s1 += v.x + v.y + v.z + v.w;
        s2 += v.x*v.x + v.y*v.y + v.z*v.z + v.w*v.w;
    }
    #pragma unroll
    for (int off = 16; off; off >>= 1) {
        s1 += __shfl_xor_sync(0xffffffffu, s1, off);
        s2 += __shfl_xor_sync(0xffffffffu, s2, off);
    }
    int warp = tid >> 5, lane = tid & 31;
    if (lane == 0) { ws1[warp] = s1; ws2[warp] = s2; }
    __syncthreads();
    if (tid == 0) {
        float t1 = 0.0f, t2 = 0.0f;
        #pragma unroll
        for (int w = 0; w < 8; w++) { t1 += ws1[w]; t2 += ws2[w]; }
        const float inv = 1.0f / (float)N_PTS;
        float mean = t1 * inv;
        float var  = t2 * inv - mean * mean;
        float gamma = buf ? gr[o] : gf[o];
        float beta  = buf ? btr[o] : btf[o];
        float A = gamma * rsqrtf(var + EPSBN);
        g_cA[buf * C_OUT + o] = A;
        g_cB[buf * C_OUT + o] = beta - mean * A;
    }
}

// ---------------------------------------------------------------------------
// Finalize: BN affine + ReLU on both paths, add, float4 throughout.
__global__ __launch_bounds__(256) void k_final(float* __restrict__ out)
{
    int i4 = blockIdx.x * 256 + threadIdx.x;    // float4 index
    int o  = i4 >> 13;                          // channel (N/4 = 8192 per row)

    float Af = g_cA[o],         Bf = g_cB[o];
    float Ar = g_cA[C_OUT + o], Br = g_cB[C_OUT + o];

    float4 y = ((const float4*)g_ypre)[i4];
    float4 r = ((const float4*)g_rpre)[i4];
    float4 v;
    v.x = fmaxf(fmaf(y.x, Af, Bf), 0.0f) + fmaxf(fmaf(r.x, Ar, Br), 0.0f);
    v.y = fmaxf(fmaf(y.y, Af, Bf), 0.0f) + fmaxf(fmaf(r.y, Ar, Br), 0.0f);
    v.z = fmaxf(fmaf(y.z, Af, Bf), 0.0f) + fmaxf(fmaf(r.z, Ar, Br), 0.0f);
    v.w = fmaxf(fmaf(y.w, Af, Bf), 0.0f) + fmaxf(fmaf(r.w, Ar, Br), 0.0f);
    ((float4*)out)[i4] = v;
}

// ---------------------------------------------------------------------------
extern "C" void kernel_launch(void* const* d_in, const int* in_sizes, int n_in,
                              void* d_out, int out_size) {
    const float* xyz   = (const float*)d_in[0];   // (1, N, 3)
    const float* pf    = (const float*)d_in[1];   // (1, 64, N)
    const float* np    = (const float*)d_in[2];   // (1, 67, N, 32)
    const float* Wint  = (const float*)d_in[3];
    const float* bint  = (const float*)d_in[4];
    const float* Wfeat = (const float*)d_in[5];
    const float* bfeat = (const float*)d_in[6];
    const float* gfeat = (const float*)d_in[7];
    const float* befeat= (const float*)d_in[8];
    const float* Wres  = (const float*)d_in[9];
    const float* bres  = (const float*)d_in[10];
    const float* gres  = (const float*)d_in[11];
    const float* beres = (const float*)d_in[12];
    float* out = (float*)d_out;

    k_fused<<<N_PTS / 32, 256>>>(xyz, np, pf, Wint, bint,
                                 Wfeat, bfeat, Wres, bres);
    k_stats<<<2 * C_OUT, 256>>>(gfeat, befeat, gres, beres);
    k_final<<<(C_OUT * N_PTS / 4) / 256, 256>>>(out);
}